// round 4
// baseline (speedup 1.0000x reference)
#include <cuda_runtime.h>
#include <cstdint>
#include <cstddef>

#define DI __device__ __forceinline__

// ---------------- problem constants ----------------
static constexpr int J       = 17;
static constexpr int FIN     = 256;
static constexpr int GB      = 8;             // batches per CTA tile
static constexpr int NROWS   = GB * J;        // 136 (MMA N)
static constexpr int THREADS = 256;           // 8 warps
static constexpr int NGRP    = 16384 / GB;    // 2048
static constexpr int KCH     = 32;            // K per chunk
static constexpr int NCH     = FIN / KCH;     // 8 chunks
static constexpr int NF      = NROWS / 8;     // 17 n-fragments

// ---------------- smem layout (float offsets) ----------------
static constexpr int S_AOFF = 0;                       // 289 floats
static constexpr int S_DIAG = 292;                     // 17 floats
static constexpr int S_BASE = 320;                     // stages & H region (16B aligned)
static constexpr int LDW    = 36;                      // padded chunk row stride (144B)
static constexpr int W0_OFF = 0;                       // 128 x 36
static constexpr int W1_OFF = 128 * LDW;               // 4608
static constexpr int X_OFF  = 256 * LDW;               // 9216
static constexpr int STAGE_FLOATS = X_OFF + NROWS * LDW;   // 14112
static constexpr int LDH    = 137;                     // odd -> conflict-free columns
static constexpr int H0_OFF = 0;
static constexpr int H1_OFF = 128 * LDH;               // 17536
static constexpr int SMEM_FLOATS = S_BASE + 2 * 128 * LDH; // 35392 (H > 2 stages)
static constexpr int SMEM_BYTES  = SMEM_FLOATS * 4;        // 141568

// ---------------- device globals (no cudaMalloc allowed) ----------------
__device__ float g_Wt[2][256][256];   // W transposed to [s][o][f], tf32-rounded (rna)
__device__ float g_Aoff[J * J];
__device__ float g_diag[J];

// ---------------- helpers ----------------
DI uint32_t smem_u32(const void* p) {
    uint32_t a;
    asm("{ .reg .u64 t; cvta.to.shared.u64 t, %1; cvt.u32.u64 %0, t; }" : "=r"(a) : "l"(p));
    return a;
}
DI uint32_t f2tf32(float f) {
    uint32_t r;
    asm("cvt.rna.tf32.f32 %0, %1;" : "=r"(r) : "f"(f));
    return r;
}
DI void cpasync16(uint32_t saddr, const void* g) {
    asm volatile("cp.async.cg.shared.global [%0], [%1], 16;" :: "r"(saddr), "l"(g) : "memory");
}
DI void cp_commit() { asm volatile("cp.async.commit_group;" ::: "memory"); }
DI void cp_wait1()  { asm volatile("cp.async.wait_group 1;" ::: "memory"); }
DI void cp_wait0()  { asm volatile("cp.async.wait_group 0;" ::: "memory"); }

// m16n8k8 tf32 warp MMA (sm_80 PTX; assembles at plain sm_100)
DI void mma8(float c[4], uint32_t a0, uint32_t a1, uint32_t a2, uint32_t a3,
             uint32_t b0, uint32_t b1) {
    asm volatile(
        "mma.sync.aligned.m16n8k8.row.col.f32.tf32.tf32.f32 "
        "{%0,%1,%2,%3}, {%4,%5,%6,%7}, {%8,%9}, {%0,%1,%2,%3};\n"
        : "+f"(c[0]), "+f"(c[1]), "+f"(c[2]), "+f"(c[3])
        : "r"(a0), "r"(a1), "r"(a2), "r"(a3), "r"(b0), "r"(b1));
}

// ---------------- prologue kernels ----------------
__global__ void mgc_prep_w(const float* __restrict__ W) {
    int s = blockIdx.x >> 8;
    int o = blockIdx.x & 255;
    int f = threadIdx.x;
    float v = W[((s << 8) + f) * 256 + o];
    g_Wt[s][o][f] = __uint_as_float(f2tf32(v));
}

__global__ void mgc_prep_adj(const float* __restrict__ adj, const float* __restrict__ adj2) {
    int idx = threadIdx.x;
    if (idx < J * J) {
        int i = idx / J, j = idx % J;
        float a  = adj[i * J + j] + adj2[i * J + j];
        float at = adj[j * J + i] + adj2[j * J + i];
        float s = 0.5f * (a + at);
        if (i == j) { g_diag[i] = s; g_Aoff[idx] = 0.0f; }
        else        { g_Aoff[idx] = s; }
    }
}

// ---------------- chunk loaders ----------------
DI void w_cp(uint32_t sstage, const float* __restrict__ w0, const float* __restrict__ w1,
             int c, int tid) {
    #pragma unroll
    for (int it = 0; it < 4; ++it) {                 // 1024 quads / 256 thr
        int idx = tid + it * THREADS;
        int row = idx >> 3, q = idx & 7;
        uint32_t so = (uint32_t)((row * LDW + q * 4) * 4);
        cpasync16(sstage + W0_OFF * 4 + so, w0 + row * FIN + c * KCH + q * 4);
        cpasync16(sstage + W1_OFF * 4 + so, w1 + row * FIN + c * KCH + q * 4);
    }
}
DI void x_ldg(float4* v, const float* __restrict__ xg, int c, int tid) {
    #pragma unroll
    for (int it = 0; it < 5; ++it) {                 // 1088 quads / 256 thr
        int idx = tid + it * THREADS;
        if (idx < NROWS * 8) {
            int row = idx >> 3, q = idx & 7;
            v[it] = *reinterpret_cast<const float4*>(xg + (size_t)row * FIN + c * KCH + q * 4);
        }
    }
}
DI void x_sts(const float4* v, float* stx, int tid) {
    #pragma unroll
    for (int it = 0; it < 5; ++it) {
        int idx = tid + it * THREADS;
        if (idx < NROWS * 8) {
            int row = idx >> 3, q = idx & 7;
            uint4 r;
            r.x = f2tf32(v[it].x); r.y = f2tf32(v[it].y);
            r.z = f2tf32(v[it].z); r.w = f2tf32(v[it].w);
            *reinterpret_cast<uint4*>(stx + row * LDW + q * 4) = r;   // 16B aligned
        }
    }
}

// ---------------- per-chunk MMA ----------------
DI void compute_chunk(const float* __restrict__ st, int warp, int g4, int t4,
                      float acc0[NF][4], float acc1[NF][4]) {
    const float* Wa = st + W0_OFF + (warp * 16 + g4) * LDW + t4;
    const float* Wb = st + W1_OFF + (warp * 16 + g4) * LDW + t4;
    const float* Xb = st + X_OFF + g4 * LDW + t4;
    #pragma unroll
    for (int ks = 0; ks < 4; ++ks) {
        const int k = ks * 8;
        uint32_t b0[NF], b1[NF];
        #pragma unroll
        for (int nf = 0; nf < NF; ++nf) {
            b0[nf] = __float_as_uint(Xb[nf * (8 * LDW) + k]);
            b1[nf] = __float_as_uint(Xb[nf * (8 * LDW) + k + 4]);
        }
        uint32_t a0 = __float_as_uint(Wa[k]);
        uint32_t a1 = __float_as_uint(Wa[8 * LDW + k]);
        uint32_t a2 = __float_as_uint(Wa[k + 4]);
        uint32_t a3 = __float_as_uint(Wa[8 * LDW + k + 4]);
        #pragma unroll
        for (int nf = 0; nf < NF; ++nf) mma8(acc0[nf], a0, a1, a2, a3, b0[nf], b1[nf]);
        a0 = __float_as_uint(Wb[k]);
        a1 = __float_as_uint(Wb[8 * LDW + k]);
        a2 = __float_as_uint(Wb[k + 4]);
        a3 = __float_as_uint(Wb[8 * LDW + k + 4]);
        #pragma unroll
        for (int nf = 0; nf < NF; ++nf) mma8(acc1[nf], a0, a1, a2, a3, b0[nf], b1[nf]);
    }
}

// ---------------- main fused kernel ----------------
__global__ void __launch_bounds__(THREADS, 1)
mgc_main(const float* __restrict__ x, const float* __restrict__ Mg,
         const float* __restrict__ bias, float* __restrict__ out) {
    extern __shared__ float smf[];
    const int tid = threadIdx.x;
    const int oh  = blockIdx.x;      // F_OUT half
    const int grp = blockIdx.y;      // batch group of 8

    for (int i = tid; i < J * J; i += THREADS) smf[S_AOFF + i] = g_Aoff[i];
    if (tid < J) smf[S_DIAG + tid] = g_diag[tid];

    const float* w0 = &g_Wt[0][oh * 128][0];
    const float* w1 = &g_Wt[1][oh * 128][0];
    const float* xg = x + (size_t)grp * NROWS * FIN;

    float* st0 = smf + S_BASE;
    float* st1 = smf + S_BASE + STAGE_FLOATS;
    const uint32_t stu0 = smem_u32(st0), stu1 = smem_u32(st1);

    // prologue: chunk 0 into stage 0
    w_cp(stu0, w0, w1, 0, tid);
    cp_commit();
    {
        float4 v[5];
        x_ldg(v, xg, 0, tid);
        x_sts(v, st0 + X_OFF, tid);
    }

    float acc0[NF][4] = {};
    float acc1[NF][4] = {};
    const int warp = tid >> 5, lane = tid & 31, g4 = lane >> 2, t4 = lane & 3;

    #pragma unroll 1
    for (int c = 0; c < NCH; ++c) {
        float4 v[5];
        float* cur = (c & 1) ? st1 : st0;
        float* nxt = (c & 1) ? st0 : st1;
        if (c + 1 < NCH) {
            w_cp((c & 1) ? stu0 : stu1, w0, w1, c + 1, tid);
            cp_commit();
            x_ldg(v, xg, c + 1, tid);       // LDGs in flight during compute
            cp_wait1();                     // chunk c's W group done
        } else {
            cp_wait0();
        }
        __syncthreads();
        compute_chunk(cur, warp, g4, t4, acc0, acc1);
        if (c + 1 < NCH) x_sts(v, nxt + X_OFF, tid);
        __syncthreads();
    }

    // ---- epilogue phase 0: fragments -> smem H0/H1 ----
    float* H0 = smf + S_BASE + H0_OFF;
    float* H1 = smf + S_BASE + H1_OFF;
    {
        const int o0 = warp * 16 + g4, n0 = 2 * t4;
        #pragma unroll
        for (int nf = 0; nf < NF; ++nf) {
            const int n = nf * 8 + n0;
            H0[o0 * LDH + n]           = acc0[nf][0];
            H0[o0 * LDH + n + 1]       = acc0[nf][1];
            H0[(o0 + 8) * LDH + n]     = acc0[nf][2];
            H0[(o0 + 8) * LDH + n + 1] = acc0[nf][3];
            H1[o0 * LDH + n]           = acc1[nf][0];
            H1[o0 * LDH + n + 1]       = acc1[nf][1];
            H1[(o0 + 8) * LDH + n]     = acc1[nf][2];
            H1[(o0 + 8) * LDH + n + 1] = acc1[nf][3];
        }
    }
    __syncthreads();

    const int o = tid & 127, half = tid >> 7;
    const int og = oh * 128 + o;

    // ---- phase 1: in-place S = bias + diag*M*h0 ; T = M*h1 ----
    {
        float m[J];
        #pragma unroll
        for (int j = 0; j < J; ++j) m[j] = Mg[j * 256 + og];
        const float bv = bias[og];
        #pragma unroll
        for (int gg = 0; gg < 4; ++gg) {
            const int g = half * 4 + gg;
            #pragma unroll
            for (int j = 0; j < J; ++j) {
                const int n = g * J + j;
                float h0v = H0[o * LDH + n];
                float h1v = H1[o * LDH + n];
                H0[o * LDH + n] = fmaf(smf[S_DIAG + j] * m[j], h0v, bv);
                H1[o * LDH + n] = m[j] * h1v;
            }
        }
    }
    __syncthreads();

    // ---- phase 2: out[b,i,o] = S[o][g*17+i] + sum_j A[i][j] * T[o][g*17+j] ----
    {
        const float* sA = smf + S_AOFF;
        const int i0 = half ? 9 : 0;                   // half0: i 0..8, half1: i 9..16
        #pragma unroll 1
        for (int tile = 0; tile < 3; ++tile) {
            const int ib = i0 + tile * 3;
            float Ar[3][J];
            #pragma unroll
            for (int u = 0; u < 3; ++u) {
                const int i = ib + u;
                #pragma unroll
                for (int j = 0; j < J; ++j)
                    Ar[u][j] = (i < J) ? sA[i * J + j] : 0.0f;
            }
            #pragma unroll 1
            for (int g = 0; g < GB; ++g) {
                float T[J];
                #pragma unroll
                for (int j = 0; j < J; ++j) T[j] = H1[o * LDH + g * J + j];
                #pragma unroll
                for (int u = 0; u < 3; ++u) {
                    const int i = ib + u;
                    if (i < J) {
                        float acc = H0[o * LDH + g * J + i];
                        #pragma unroll
                        for (int j = 0; j < J; ++j) acc = fmaf(Ar[u][j], T[j], acc);
                        out[((size_t)(grp * GB + g) * J + i) * 256 + og] = acc;
                    }
                }
            }
        }
    }
}

// ---------------- launch ----------------
extern "C" void kernel_launch(void* const* d_in, const int* in_sizes, int n_in,
                              void* d_out, int out_size) {
    const float* x    = (const float*)d_in[0];
    const float* W    = (const float*)d_in[1];
    const float* Mg   = (const float*)d_in[2];
    const float* adj  = (const float*)d_in[3];
    const float* adj2 = (const float*)d_in[4];
    const float* bias = (const float*)d_in[5];
    float* out = (float*)d_out;
    (void)in_sizes; (void)n_in; (void)out_size;

    cudaFuncSetAttribute(mgc_main, cudaFuncAttributeMaxDynamicSharedMemorySize, SMEM_BYTES);

    mgc_prep_w<<<512, 256>>>(W);
    mgc_prep_adj<<<1, 320>>>(adj, adj2);
    mgc_main<<<dim3(2, NGRP), THREADS, SMEM_BYTES>>>(x, Mg, bias, out);
}

// round 5
// speedup vs baseline: 1.0230x; 1.0230x over previous
#include <cuda_runtime.h>
#include <cstdint>
#include <cstddef>

#define DI __device__ __forceinline__

// ---------------- problem constants ----------------
static constexpr int J       = 17;
static constexpr int FIN     = 256;
static constexpr int GB      = 4;             // batches per CTA tile
static constexpr int NROWS   = GB * J;        // 68 real N
static constexpr int NPAD    = 72;            // padded to 9 fragments of 8
static constexpr int NF      = NPAD / 8;      // 9
static constexpr int THREADS = 256;           // 8 warps
static constexpr int NGRP    = 16384 / GB;    // 4096
static constexpr int KCH     = 32;            // K per chunk
static constexpr int NCH     = FIN / KCH;     // 8 chunks

// ---------------- smem layout (float offsets) ----------------
static constexpr int S_AOFF = 0;                       // 289 floats
static constexpr int S_DIAG = 292;                     // 17 floats
static constexpr int S_BASE = 320;                     // stages & H region (16B aligned)
static constexpr int LDW    = 36;                      // padded chunk row stride
static constexpr int W0_OFF = 0;                       // 128 x 36
static constexpr int W1_OFF = 128 * LDW;               // 4608
static constexpr int X_OFF  = 256 * LDW;               // 9216
static constexpr int STAGE_FLOATS = X_OFF + NPAD * LDW;    // 11808 (47.2 KB)
static constexpr int LDH    = 73;                      // 73 mod 32 = 9 (coprime) -> conflict-free
static constexpr int H0_OFF = 0;
static constexpr int H1_OFF = 128 * LDH;               // 9344
static constexpr int SMEM_FLOATS = S_BASE + 2 * STAGE_FLOATS;  // 23936  (H: 18688 < 23616, reuses stages)
static constexpr int SMEM_BYTES  = SMEM_FLOATS * 4;            // 95744  -> 2 CTAs/SM

// ---------------- device globals (no cudaMalloc allowed) ----------------
__device__ float g_Wt[2][256][256];   // W transposed to [s][o][f], tf32-rounded (rna)
__device__ float g_Aoff[J * J];
__device__ float g_diag[J];

// ---------------- helpers ----------------
DI uint32_t smem_u32(const void* p) {
    uint32_t a;
    asm("{ .reg .u64 t; cvta.to.shared.u64 t, %1; cvt.u32.u64 %0, t; }" : "=r"(a) : "l"(p));
    return a;
}
DI uint32_t f2tf32(float f) {
    uint32_t r;
    asm("cvt.rna.tf32.f32 %0, %1;" : "=r"(r) : "f"(f));
    return r;
}
DI void cpasync16(uint32_t saddr, const void* g) {
    asm volatile("cp.async.cg.shared.global [%0], [%1], 16;" :: "r"(saddr), "l"(g) : "memory");
}
DI void cp_commit() { asm volatile("cp.async.commit_group;" ::: "memory"); }
DI void cp_wait1()  { asm volatile("cp.async.wait_group 1;" ::: "memory"); }
DI void cp_wait0()  { asm volatile("cp.async.wait_group 0;" ::: "memory"); }

// m16n8k8 tf32 warp MMA (sm_80 PTX; assembles at plain sm_100)
DI void mma8(float c[4], uint32_t a0, uint32_t a1, uint32_t a2, uint32_t a3,
             uint32_t b0, uint32_t b1) {
    asm volatile(
        "mma.sync.aligned.m16n8k8.row.col.f32.tf32.tf32.f32 "
        "{%0,%1,%2,%3}, {%4,%5,%6,%7}, {%8,%9}, {%0,%1,%2,%3};\n"
        : "+f"(c[0]), "+f"(c[1]), "+f"(c[2]), "+f"(c[3])
        : "r"(a0), "r"(a1), "r"(a2), "r"(a3), "r"(b0), "r"(b1));
}

// ---------------- prologue kernels ----------------
__global__ void mgc_prep_w(const float* __restrict__ W) {
    int s = blockIdx.x >> 8;
    int o = blockIdx.x & 255;
    int f = threadIdx.x;
    float v = W[((s << 8) + f) * 256 + o];
    g_Wt[s][o][f] = __uint_as_float(f2tf32(v));
}

__global__ void mgc_prep_adj(const float* __restrict__ adj, const float* __restrict__ adj2) {
    int idx = threadIdx.x;
    if (idx < J * J) {
        int i = idx / J, j = idx % J;
        float a  = adj[i * J + j] + adj2[i * J + j];
        float at = adj[j * J + i] + adj2[j * J + i];
        float s = 0.5f * (a + at);
        if (i == j) { g_diag[i] = s; g_Aoff[idx] = 0.0f; }
        else        { g_Aoff[idx] = s; }
    }
}

// ---------------- chunk loaders ----------------
DI void w_cp(uint32_t sstage, const float* __restrict__ w0, const float* __restrict__ w1,
             int c, int tid) {
    #pragma unroll
    for (int it = 0; it < 4; ++it) {                 // 1024 quads each / 256 thr
        int idx = tid + it * THREADS;
        int row = idx >> 3, q = idx & 7;
        uint32_t so = (uint32_t)((row * LDW + q * 4) * 4);
        cpasync16(sstage + W0_OFF * 4 + so, w0 + row * FIN + c * KCH + q * 4);
        cpasync16(sstage + W1_OFF * 4 + so, w1 + row * FIN + c * KCH + q * 4);
    }
}
DI void x_ldg(float4* v, const float* __restrict__ xg, int c, int tid) {
    #pragma unroll
    for (int it = 0; it < 3; ++it) {                 // 544 quads / 256 thr
        int idx = tid + it * THREADS;
        if (idx < NROWS * 8) {
            int row = idx >> 3, q = idx & 7;
            v[it] = *reinterpret_cast<const float4*>(xg + (size_t)row * FIN + c * KCH + q * 4);
        }
    }
}
DI void x_sts(const float4* v, float* stx, int tid) {
    #pragma unroll
    for (int it = 0; it < 3; ++it) {
        int idx = tid + it * THREADS;
        if (idx < NROWS * 8) {
            int row = idx >> 3, q = idx & 7;
            uint4 r;
            r.x = f2tf32(v[it].x); r.y = f2tf32(v[it].y);
            r.z = f2tf32(v[it].z); r.w = f2tf32(v[it].w);
            *reinterpret_cast<uint4*>(stx + row * LDW + q * 4) = r;   // 16B aligned
        }
    }
}

// ---------------- per-chunk MMA ----------------
DI void compute_chunk(const float* __restrict__ st, int warp, int g4, int t4,
                      float acc0[NF][4], float acc1[NF][4]) {
    const float* Wa = st + W0_OFF + (warp * 16 + g4) * LDW + t4;
    const float* Wb = st + W1_OFF + (warp * 16 + g4) * LDW + t4;
    const float* Xb = st + X_OFF + g4 * LDW + t4;
    #pragma unroll
    for (int ks = 0; ks < 4; ++ks) {
        const int k = ks * 8;
        uint32_t b0[NF], b1[NF];
        #pragma unroll
        for (int nf = 0; nf < NF; ++nf) {
            b0[nf] = __float_as_uint(Xb[nf * (8 * LDW) + k]);
            b1[nf] = __float_as_uint(Xb[nf * (8 * LDW) + k + 4]);
        }
        uint32_t a0 = __float_as_uint(Wa[k]);
        uint32_t a1 = __float_as_uint(Wa[8 * LDW + k]);
        uint32_t a2 = __float_as_uint(Wa[k + 4]);
        uint32_t a3 = __float_as_uint(Wa[8 * LDW + k + 4]);
        #pragma unroll
        for (int nf = 0; nf < NF; ++nf) mma8(acc0[nf], a0, a1, a2, a3, b0[nf], b1[nf]);
        a0 = __float_as_uint(Wb[k]);
        a1 = __float_as_uint(Wb[8 * LDW + k]);
        a2 = __float_as_uint(Wb[k + 4]);
        a3 = __float_as_uint(Wb[8 * LDW + k + 4]);
        #pragma unroll
        for (int nf = 0; nf < NF; ++nf) mma8(acc1[nf], a0, a1, a2, a3, b0[nf], b1[nf]);
    }
}

// ---------------- main fused kernel ----------------
__global__ void __launch_bounds__(THREADS, 2)
mgc_main(const float* __restrict__ x, const float* __restrict__ Mg,
         const float* __restrict__ bias, float* __restrict__ out) {
    extern __shared__ float smf[];
    const int tid = threadIdx.x;
    const int oh  = blockIdx.x;      // F_OUT half
    const int grp = blockIdx.y;      // batch group of GB

    for (int i = tid; i < J * J; i += THREADS) smf[S_AOFF + i] = g_Aoff[i];
    if (tid < J) smf[S_DIAG + tid] = g_diag[tid];

    const float* w0 = &g_Wt[0][oh * 128][0];
    const float* w1 = &g_Wt[1][oh * 128][0];
    const float* xg = x + (size_t)grp * NROWS * FIN;

    float* st0 = smf + S_BASE;
    float* st1 = smf + S_BASE + STAGE_FLOATS;
    const uint32_t stu0 = smem_u32(st0), stu1 = smem_u32(st1);

    // prologue: chunk 0 into stage 0
    w_cp(stu0, w0, w1, 0, tid);
    cp_commit();
    {
        float4 v[3];
        x_ldg(v, xg, 0, tid);
        x_sts(v, st0 + X_OFF, tid);
    }

    float acc0[NF][4] = {};
    float acc1[NF][4] = {};
    const int warp = tid >> 5, lane = tid & 31, g4 = lane >> 2, t4 = lane & 3;

    #pragma unroll 1
    for (int c = 0; c < NCH; ++c) {
        float4 v[3];
        float* cur = (c & 1) ? st1 : st0;
        float* nxt = (c & 1) ? st0 : st1;
        if (c + 1 < NCH) {
            w_cp((c & 1) ? stu0 : stu1, w0, w1, c + 1, tid);
            cp_commit();
            x_ldg(v, xg, c + 1, tid);       // LDGs in flight during compute
            cp_wait1();                     // chunk c's W group done
        } else {
            cp_wait0();
        }
        __syncthreads();
        compute_chunk(cur, warp, g4, t4, acc0, acc1);
        if (c + 1 < NCH) x_sts(v, nxt + X_OFF, tid);
        __syncthreads();
    }

    // ---- epilogue phase 0: fragments -> smem H0/H1 (padding cols land in-row, LDH=73) ----
    float* H0 = smf + S_BASE + H0_OFF;
    float* H1 = smf + S_BASE + H1_OFF;
    {
        const int o0 = warp * 16 + g4, n0 = 2 * t4;
        #pragma unroll
        for (int nf = 0; nf < NF; ++nf) {
            const int n = nf * 8 + n0;
            H0[o0 * LDH + n]           = acc0[nf][0];
            H0[o0 * LDH + n + 1]       = acc0[nf][1];
            H0[(o0 + 8) * LDH + n]     = acc0[nf][2];
            H0[(o0 + 8) * LDH + n + 1] = acc0[nf][3];
            H1[o0 * LDH + n]           = acc1[nf][0];
            H1[o0 * LDH + n + 1]       = acc1[nf][1];
            H1[(o0 + 8) * LDH + n]     = acc1[nf][2];
            H1[(o0 + 8) * LDH + n + 1] = acc1[nf][3];
        }
    }
    __syncthreads();

    const int o = tid & 127, half = tid >> 7;
    const int og = oh * 128 + o;

    // ---- phase 1: in-place S = bias + diag*M*h0 ; T = M*h1 ----
    {
        float m[J];
        #pragma unroll
        for (int j = 0; j < J; ++j) m[j] = Mg[j * 256 + og];
        const float bv = bias[og];
        #pragma unroll
        for (int gg = 0; gg < GB / 2; ++gg) {
            const int g = half * (GB / 2) + gg;
            #pragma unroll
            for (int j = 0; j < J; ++j) {
                const int n = g * J + j;
                float h0v = H0[o * LDH + n];
                float h1v = H1[o * LDH + n];
                H0[o * LDH + n] = fmaf(smf[S_DIAG + j] * m[j], h0v, bv);
                H1[o * LDH + n] = m[j] * h1v;
            }
        }
    }
    __syncthreads();

    // ---- phase 2: out[b,i,o] = S[o][g*17+i] + sum_j A[i][j] * T[o][g*17+j] ----
    {
        const float* sA = smf + S_AOFF;
        const int i0 = half ? 9 : 0;                   // half0: i 0..8, half1: i 9..16
        #pragma unroll 1
        for (int tile = 0; tile < 3; ++tile) {
            const int ib = i0 + tile * 3;
            float Ar[3][J];
            #pragma unroll
            for (int u = 0; u < 3; ++u) {
                const int i = ib + u;
                #pragma unroll
                for (int j = 0; j < J; ++j)
                    Ar[u][j] = (i < J) ? sA[i * J + j] : 0.0f;
            }
            #pragma unroll 1
            for (int g = 0; g < GB; ++g) {
                float T[J];
                #pragma unroll
                for (int j = 0; j < J; ++j) T[j] = H1[o * LDH + g * J + j];
                #pragma unroll
                for (int u = 0; u < 3; ++u) {
                    const int i = ib + u;
                    if (i < J) {
                        float acc = H0[o * LDH + g * J + i];
                        #pragma unroll
                        for (int j = 0; j < J; ++j) acc = fmaf(Ar[u][j], T[j], acc);
                        out[((size_t)(grp * GB + g) * J + i) * 256 + og] = acc;
                    }
                }
            }
        }
    }
}

// ---------------- launch ----------------
extern "C" void kernel_launch(void* const* d_in, const int* in_sizes, int n_in,
                              void* d_out, int out_size) {
    const float* x    = (const float*)d_in[0];
    const float* W    = (const float*)d_in[1];
    const float* Mg   = (const float*)d_in[2];
    const float* adj  = (const float*)d_in[3];
    const float* adj2 = (const float*)d_in[4];
    const float* bias = (const float*)d_in[5];
    float* out = (float*)d_out;
    (void)in_sizes; (void)n_in; (void)out_size;

    cudaFuncSetAttribute(mgc_main, cudaFuncAttributeMaxDynamicSharedMemorySize, SMEM_BYTES);

    mgc_prep_w<<<512, 256>>>(W);
    mgc_prep_adj<<<1, 320>>>(adj, adj2);
    mgc_main<<<dim3(2, NGRP), THREADS, SMEM_BYTES>>>(x, Mg, bias, out);
}

// round 6
// speedup vs baseline: 1.5367x; 1.5021x over previous
#include <cuda_runtime.h>
#include <cstdint>
#include <cstddef>

#define DI __device__ __forceinline__

// ---------------- problem constants ----------------
static constexpr int J       = 17;
static constexpr int FIN     = 256;
static constexpr int GB      = 4;             // batches per CTA tile
static constexpr int NROWS   = GB * J;        // 68 real N rows
static constexpr int NPAD    = 72;            // padded to 9 fragments of 8
static constexpr int NF      = NPAD / 8;      // 9
static constexpr int THREADS = 256;           // 8 warps
static constexpr int NGRP    = 16384 / GB;    // 4096
static constexpr int KCH     = 64;            // K elements per chunk (fp16: 128 B/row)
static constexpr int NCH     = FIN / KCH;     // 4 chunks
static constexpr int KS      = KCH / 16;      // 4 k-steps (m16n8k16) per chunk

// ---------------- smem layout ----------------
// u32 units. Row stride LDR=36 u32 (=72 halves =144 B): 144%16==0 (cp.async align),
// bank: (36*g8 + t4) mod 32 = 4*g8 + t4 -> all 32 lanes distinct, conflict-free.
static constexpr int S_AOFF = 0;                    // 289 f32
static constexpr int S_DIAG = 292;                  // 17 f32
static constexpr int S_BASE = 320;                  // 16B aligned (1280 B)
static constexpr int LDR    = 36;                   // u32 per row
static constexpr int W_ROWS = 256;                  // W0: rows 0..127, W1: 128..255
static constexpr int X_ROW0 = 256;                  // X rows 256..327 (72 rows)
static constexpr int STAGE_U32 = (W_ROWS + NPAD) * LDR;   // 328*36 = 11808
static constexpr int LDH    = 73;                   // f32 H stride, odd -> conflict-free
static constexpr int SMEM_U32 = S_BASE + 2 * STAGE_U32;   // 23936
static constexpr int SMEM_BYTES = SMEM_U32 * 4;           // 95744 -> 2 CTAs/SM
// H region (f32) reuses stage area: 2*128*73 = 18688 f32 <= 23616 u32  OK

// ---------------- device globals (no cudaMalloc allowed) ----------------
__device__ uint32_t g_Wh[2][256][128];   // W as half2, [s][o][f/2], rn-rounded
__device__ float g_Aoff[J * J];
__device__ float g_diag[J];

// ---------------- helpers ----------------
DI uint32_t smem_u32p(const void* p) {
    uint32_t a;
    asm("{ .reg .u64 t; cvta.to.shared.u64 t, %1; cvt.u32.u64 %0, t; }" : "=r"(a) : "l"(p));
    return a;
}
DI uint32_t pack_h2(float lo, float hi) {   // low half <- lo (lower k index)
    uint32_t r;
    asm("cvt.rn.f16x2.f32 %0, %1, %2;" : "=r"(r) : "f"(hi), "f"(lo));
    return r;
}
DI void cpasync16(uint32_t saddr, const void* g) {
    asm volatile("cp.async.cg.shared.global [%0], [%1], 16;" :: "r"(saddr), "l"(g) : "memory");
}
DI void cp_commit() { asm volatile("cp.async.commit_group;" ::: "memory"); }
DI void cp_wait1()  { asm volatile("cp.async.wait_group 1;" ::: "memory"); }
DI void cp_wait0()  { asm volatile("cp.async.wait_group 0;" ::: "memory"); }
DI void sts64(uint32_t a, uint32_t x0, uint32_t x1) {
    asm volatile("st.shared.v2.b32 [%0], {%1,%2};" :: "r"(a), "r"(x0), "r"(x1) : "memory");
}

// m16n8k16 fp16 MMA, fp32 accumulate (sm_80 PTX; assembles at plain sm_100)
DI void mma16(float c[4], uint32_t a0, uint32_t a1, uint32_t a2, uint32_t a3,
              uint32_t b0, uint32_t b1) {
    asm volatile(
        "mma.sync.aligned.m16n8k16.row.col.f32.f16.f16.f32 "
        "{%0,%1,%2,%3}, {%4,%5,%6,%7}, {%8,%9}, {%0,%1,%2,%3};\n"
        : "+f"(c[0]), "+f"(c[1]), "+f"(c[2]), "+f"(c[3])
        : "r"(a0), "r"(a1), "r"(a2), "r"(a3), "r"(b0), "r"(b1));
}

// ---------------- single prologue kernel (W pack + adj fold) ----------------
__global__ void mgc_prep(const float* __restrict__ W,
                         const float* __restrict__ adj, const float* __restrict__ adj2) {
    int s = blockIdx.x >> 8;
    int o = blockIdx.x & 255;
    int t = threadIdx.x;                       // 128 threads: f pair = 2t, 2t+1
    float v0 = W[((s << 8) + 2 * t) * 256 + o];
    float v1 = W[((s << 8) + 2 * t + 1) * 256 + o];
    g_Wh[s][o][t] = pack_h2(v0, v1);
    if (blockIdx.x == 0) {
        for (int idx = t; idx < J * J; idx += 128) {
            int i = idx / J, j = idx % J;
            float a  = adj[i * J + j] + adj2[i * J + j];
            float at = adj[j * J + i] + adj2[j * J + i];
            float sv = 0.5f * (a + at);
            if (i == j) { g_diag[i] = sv; g_Aoff[idx] = 0.0f; }
            else        { g_Aoff[idx] = sv; }
        }
    }
}

// ---------------- chunk loaders ----------------
DI void w_cp(uint32_t sstage, const uint32_t* __restrict__ w0,
             const uint32_t* __restrict__ w1, int c, int tid) {
    #pragma unroll
    for (int it = 0; it < 8; ++it) {                 // 2048 quads / 256 thr
        int idx = tid + it * THREADS;
        int row = idx >> 3, q = idx & 7;
        const uint32_t* src = (row < 128) ? (w0 + row * 128 + c * 32 + q * 4)
                                          : (w1 + (row - 128) * 128 + c * 32 + q * 4);
        cpasync16(sstage + (uint32_t)(row * LDR + q * 4) * 4, src);
    }
}
DI void x_ldg(float4* v, const float* __restrict__ xg, int c, int tid) {
    #pragma unroll
    for (int it = 0; it < 5; ++it) {                 // 1088 float4 / 256 thr
        int idx = tid + it * THREADS;
        if (idx < NROWS * 16) {
            int row = idx >> 4, q = idx & 15;
            v[it] = *reinterpret_cast<const float4*>(xg + (size_t)row * FIN + c * KCH + q * 4);
        }
    }
}
DI void x_sts(const float4* v, uint32_t sstage, int tid) {
    #pragma unroll
    for (int it = 0; it < 5; ++it) {
        int idx = tid + it * THREADS;
        if (idx < NROWS * 16) {
            int row = idx >> 4, q = idx & 15;
            uint32_t p0 = pack_h2(v[it].x, v[it].y);
            uint32_t p1 = pack_h2(v[it].z, v[it].w);
            sts64(sstage + (uint32_t)((X_ROW0 + row) * LDR + q * 2) * 4, p0, p1);
        }
    }
}

// ---------------- per-chunk MMA ----------------
DI void compute_chunk(const uint32_t* __restrict__ st, int warp, int g8, int t4,
                      float acc0[NF][4], float acc1[NF][4]) {
    const uint32_t* A0 = st + (warp * 16) * LDR + t4;
    const uint32_t* A1 = st + (128 + warp * 16) * LDR + t4;
    const uint32_t* XB = st + (X_ROW0 + g8) * LDR + t4;
    #pragma unroll
    for (int ks = 0; ks < KS; ++ks) {
        const int off = ks * 8;
        uint32_t b0[NF], b1[NF];
        #pragma unroll
        for (int nf = 0; nf < NF; ++nf) {
            b0[nf] = XB[nf * (8 * LDR) + off];
            b1[nf] = XB[nf * (8 * LDR) + off + 4];
        }
        uint32_t a0 = A0[g8 * LDR + off];
        uint32_t a1 = A0[(g8 + 8) * LDR + off];
        uint32_t a2 = A0[g8 * LDR + off + 4];
        uint32_t a3 = A0[(g8 + 8) * LDR + off + 4];
        #pragma unroll
        for (int nf = 0; nf < NF; ++nf) mma16(acc0[nf], a0, a1, a2, a3, b0[nf], b1[nf]);
        a0 = A1[g8 * LDR + off];
        a1 = A1[(g8 + 8) * LDR + off];
        a2 = A1[g8 * LDR + off + 4];
        a3 = A1[(g8 + 8) * LDR + off + 4];
        #pragma unroll
        for (int nf = 0; nf < NF; ++nf) mma16(acc1[nf], a0, a1, a2, a3, b0[nf], b1[nf]);
    }
}

// ---------------- main fused kernel ----------------
__global__ void __launch_bounds__(THREADS, 2)
mgc_main(const float* __restrict__ x, const float* __restrict__ Mg,
         const float* __restrict__ bias, float* __restrict__ out) {
    extern __shared__ float smf[];
    uint32_t* smu = reinterpret_cast<uint32_t*>(smf);
    const int tid = threadIdx.x;
    const int oh  = blockIdx.x;      // F_OUT half
    const int grp = blockIdx.y;      // batch group of GB

    for (int i = tid; i < J * J; i += THREADS) smf[S_AOFF + i] = g_Aoff[i];
    if (tid < J) smf[S_DIAG + tid] = g_diag[tid];

    const uint32_t* w0 = &g_Wh[0][oh * 128][0];
    const uint32_t* w1 = &g_Wh[1][oh * 128][0];
    const float* xg = x + (size_t)grp * NROWS * FIN;

    const uint32_t* st0 = smu + S_BASE;
    const uint32_t* st1 = smu + S_BASE + STAGE_U32;
    const uint32_t stu0 = smem_u32p(st0), stu1 = smem_u32p(st1);

    // prologue: chunk 0 into stage 0
    w_cp(stu0, w0, w1, 0, tid);
    cp_commit();
    {
        float4 v[5];
        x_ldg(v, xg, 0, tid);
        x_sts(v, stu0, tid);
    }

    float acc0[NF][4] = {};
    float acc1[NF][4] = {};
    const int warp = tid >> 5, lane = tid & 31, g8 = lane >> 2, t4 = lane & 3;

    #pragma unroll 1
    for (int c = 0; c < NCH; ++c) {
        float4 v[5];
        const uint32_t* cur = (c & 1) ? st1 : st0;
        if (c + 1 < NCH) {
            w_cp((c & 1) ? stu0 : stu1, w0, w1, c + 1, tid);
            cp_commit();
            x_ldg(v, xg, c + 1, tid);       // LDGs in flight during compute
            cp_wait1();                     // chunk c's W group complete
        } else {
            cp_wait0();
        }
        __syncthreads();
        compute_chunk(cur, warp, g8, t4, acc0, acc1);
        if (c + 1 < NCH) x_sts(v, (c & 1) ? stu0 : stu1, tid);
        __syncthreads();
    }

    // ---- epilogue phase 0: fragments -> smem H0/H1 (f32, reuses stage area) ----
    float* H0 = smf + S_BASE;
    float* H1 = smf + S_BASE + 128 * LDH;
    {
        const int o0 = warp * 16 + g8, n0 = 2 * t4;
        #pragma unroll
        for (int nf = 0; nf < NF; ++nf) {
            const int n = nf * 8 + n0;
            H0[o0 * LDH + n]           = acc0[nf][0];
            H0[o0 * LDH + n + 1]       = acc0[nf][1];
            H0[(o0 + 8) * LDH + n]     = acc0[nf][2];
            H0[(o0 + 8) * LDH + n + 1] = acc0[nf][3];
            H1[o0 * LDH + n]           = acc1[nf][0];
            H1[o0 * LDH + n + 1]       = acc1[nf][1];
            H1[(o0 + 8) * LDH + n]     = acc1[nf][2];
            H1[(o0 + 8) * LDH + n + 1] = acc1[nf][3];
        }
    }
    __syncthreads();

    const int o = tid & 127, half = tid >> 7;
    const int og = oh * 128 + o;

    // ---- phase 1: in-place S = bias + diag*M*h0 ; T = M*h1 ----
    {
        float m[J];
        #pragma unroll
        for (int j = 0; j < J; ++j) m[j] = Mg[j * 256 + og];
        const float bv = bias[og];
        #pragma unroll
        for (int gg = 0; gg < GB / 2; ++gg) {
            const int g = half * (GB / 2) + gg;
            #pragma unroll
            for (int j = 0; j < J; ++j) {
                const int n = g * J + j;
                float h0v = H0[o * LDH + n];
                float h1v = H1[o * LDH + n];
                H0[o * LDH + n] = fmaf(smf[S_DIAG + j] * m[j], h0v, bv);
                H1[o * LDH + n] = m[j] * h1v;
            }
        }
    }
    __syncthreads();

    // ---- phase 2: out[b,i,o] = S[o][g*17+i] + sum_j A[i][j] * T[o][g*17+j] ----
    {
        const float* sA = smf + S_AOFF;
        const int i0 = half ? 9 : 0;
        #pragma unroll 1
        for (int tile = 0; tile < 3; ++tile) {
            const int ib = i0 + tile * 3;
            float Ar[3][J];
            #pragma unroll
            for (int u = 0; u < 3; ++u) {
                const int i = ib + u;
                #pragma unroll
                for (int j = 0; j < J; ++j)
                    Ar[u][j] = (i < J) ? sA[i * J + j] : 0.0f;
            }
            #pragma unroll 1
            for (int g = 0; g < GB; ++g) {
                float T[J];
                #pragma unroll
                for (int j = 0; j < J; ++j) T[j] = H1[o * LDH + g * J + j];
                #pragma unroll
                for (int u = 0; u < 3; ++u) {
                    const int i = ib + u;
                    if (i < J) {
                        float acc = H0[o * LDH + g * J + i];
                        #pragma unroll
                        for (int j = 0; j < J; ++j) acc = fmaf(Ar[u][j], T[j], acc);
                        out[((size_t)(grp * GB + g) * J + i) * 256 + og] = acc;
                    }
                }
            }
        }
    }
}

// ---------------- launch ----------------
extern "C" void kernel_launch(void* const* d_in, const int* in_sizes, int n_in,
                              void* d_out, int out_size) {
    const float* x    = (const float*)d_in[0];
    const float* W    = (const float*)d_in[1];
    const float* Mg   = (const float*)d_in[2];
    const float* adj  = (const float*)d_in[3];
    const float* adj2 = (const float*)d_in[4];
    const float* bias = (const float*)d_in[5];
    float* out = (float*)d_out;
    (void)in_sizes; (void)n_in; (void)out_size;

    cudaFuncSetAttribute(mgc_main, cudaFuncAttributeMaxDynamicSharedMemorySize, SMEM_BYTES);

    mgc_prep<<<512, 128>>>(W, adj, adj2);
    mgc_main<<<dim3(2, NGRP), THREADS, SMEM_BYTES>>>(x, Mg, bias, out);
}